// round 1
// baseline (speedup 1.0000x reference)
#include <cuda_runtime.h>
#include <cstdint>

#define BB   256
#define TT   2048
#define FIN  9
#define C1   16
#define C2   32
#define T1   1024
#define TPP  512
#define NN   131072
#define EE   2097152
#define HID  64
#define TW   260

// ---------------- scratch (static device globals; no runtime alloc) ----------
__device__ int   d_cnt[NN];
__device__ int   d_ptr[NN];
__device__ int   d_cur[NN];
__device__ int   d_bsum[128];
__device__ int   d_srow[EE];
__device__ float d_dinv[NN];
__device__ float d_h1[(size_t)BB * T1 * C1];      // conv1 output (B, T1, 16)
__device__ float d_gA[(size_t)NN * HID];          // ping
__device__ float d_hB[(size_t)NN * HID];          // pong

// ---------------- graph prep -------------------------------------------------
__global__ void zero_cnt_kernel() {
    d_cnt[blockIdx.x * 1024 + threadIdx.x] = 0;
}

__global__ void hist_kernel(const int* __restrict__ col) {
    int e = blockIdx.x * blockDim.x + threadIdx.x;
    atomicAdd(&d_cnt[col[e]], 1);
}

__global__ void scan_block_kernel() {
    __shared__ int s[1024];
    int i = blockIdx.x * 1024 + threadIdx.x;
    int v = d_cnt[i];
    s[threadIdx.x] = v;
    __syncthreads();
    #pragma unroll
    for (int off = 1; off < 1024; off <<= 1) {
        int t = (threadIdx.x >= off) ? s[threadIdx.x - off] : 0;
        __syncthreads();
        s[threadIdx.x] += t;
        __syncthreads();
    }
    d_ptr[i] = s[threadIdx.x] - v;          // exclusive
    if (threadIdx.x == 1023) d_bsum[blockIdx.x] = s[1023];
}

__global__ void scan_sums_kernel() {
    __shared__ int s[128];
    int v = d_bsum[threadIdx.x];
    s[threadIdx.x] = v;
    __syncthreads();
    #pragma unroll
    for (int off = 1; off < 128; off <<= 1) {
        int t = (threadIdx.x >= off) ? s[threadIdx.x - off] : 0;
        __syncthreads();
        s[threadIdx.x] += t;
        __syncthreads();
    }
    d_bsum[threadIdx.x] = s[threadIdx.x] - v;  // exclusive block offsets
}

__global__ void finalize_kernel() {
    int i = blockIdx.x * 1024 + threadIdx.x;
    int p = d_ptr[i] + d_bsum[blockIdx.x];
    d_ptr[i] = p;
    d_cur[i] = p;
    d_dinv[i] = rsqrtf((float)d_cnt[i] + 1.0f);   // +1 for the self loop
}

__global__ void scatter_kernel(const int* __restrict__ row, const int* __restrict__ col) {
    int e = blockIdx.x * blockDim.x + threadIdx.x;
    int c = col[e];
    int p = atomicAdd(&d_cur[c], 1);
    d_srow[p] = row[e];
}

// ---------------- conv1: (B,T,9) -> relu -> pool2 -> (B,T1,16) ---------------
__global__ void conv1_kernel(const float* __restrict__ x,
                             const float* __restrict__ w,
                             const float* __restrict__ bias) {
    __shared__ __align__(16) float xs[TW * 9];      // input window
    __shared__ __align__(16) float ws[720];         // transposed: [(f*5+k)*16 + c]
    __shared__ float bs[16];
    int b = blockIdx.y, tp0 = blockIdx.x * 128, tid = threadIdx.x;

    for (int j = tid; j < 720; j += 128) {
        int c = j & 15, r = j >> 4, f = r / 5, k = r - f * 5;
        ws[j] = w[c * 45 + f * 5 + k];
    }
    if (tid < 16) bs[tid] = bias[tid];

    int base = 2 * tp0 - 2;
    const float* xb = x + (size_t)b * TT * FIN;
    for (int j = tid; j < TW * 9; j += 128) {
        int t = base + j / 9, f = j - (j / 9) * 9;
        xs[j] = (t >= 0 && t < TT) ? xb[t * 9 + f] : 0.0f;
    }
    __syncthreads();

    float s0[16], s1[16];
    #pragma unroll
    for (int c = 0; c < 16; c++) { s0[c] = 0.f; s1[c] = 0.f; }

    #pragma unroll
    for (int f = 0; f < 9; f++) {
        float v[6];
        #pragma unroll
        for (int j = 0; j < 6; j++) v[j] = xs[(2 * tid + j) * 9 + f];
        #pragma unroll
        for (int k = 0; k < 5; k++) {
            const float4* wr = (const float4*)&ws[(f * 5 + k) * 16];
            float a = v[k], bb = v[k + 1];
            #pragma unroll
            for (int q = 0; q < 4; q++) {
                float4 w4 = wr[q];
                s0[q*4+0] += w4.x * a;  s1[q*4+0] += w4.x * bb;
                s0[q*4+1] += w4.y * a;  s1[q*4+1] += w4.y * bb;
                s0[q*4+2] += w4.z * a;  s1[q*4+2] += w4.z * bb;
                s0[q*4+3] += w4.w * a;  s1[q*4+3] += w4.w * bb;
            }
        }
    }

    float4* out = (float4*)(d_h1 + ((size_t)b * T1 + tp0 + tid) * 16);
    #pragma unroll
    for (int q = 0; q < 4; q++) {
        float4 o;
        o.x = fmaxf(fmaxf(s0[q*4+0], s1[q*4+0]) + bs[q*4+0], 0.f);
        o.y = fmaxf(fmaxf(s0[q*4+1], s1[q*4+1]) + bs[q*4+1], 0.f);
        o.z = fmaxf(fmaxf(s0[q*4+2], s1[q*4+2]) + bs[q*4+2], 0.f);
        o.w = fmaxf(fmaxf(s0[q*4+3], s1[q*4+3]) + bs[q*4+3], 0.f);
        out[q] = o;
    }
}

// ---------------- conv2 + GEMM1: nodes h(32) -> g1 = (h@W1)*dinv ------------
__global__ void conv2_g1_kernel(const float* __restrict__ w2,
                                const float* __restrict__ b2,
                                const float* __restrict__ w1g) {
    __shared__ __align__(16) float buf[TW * 16];    // phase1: h1 window; phase2: W1 (2048)
    __shared__ __align__(16) float ws[2560];        // transposed: [(ci*5+k)*32 + c]
    __shared__ __align__(16) float h2s[32 * 128];   // [c][tp]
    __shared__ float bs[32];
    int b = blockIdx.y, tpb = blockIdx.x * 128, tid = threadIdx.x;

    for (int j = tid; j < 2560; j += 128) {
        int c = j & 31, r = j >> 5, ci = r / 5, k = r - ci * 5;
        ws[j] = w2[c * 80 + ci * 5 + k];
    }
    if (tid < 32) bs[tid] = b2[tid];

    int base = 2 * tpb - 2;
    const float* hb = d_h1 + (size_t)b * T1 * 16;
    for (int j = tid; j < TW * 16; j += 128) {
        int t = base + (j >> 4);
        buf[j] = (t >= 0 && t < T1) ? hb[t * 16 + (j & 15)] : 0.0f;
    }
    __syncthreads();

    float s0[32], s1[32];
    #pragma unroll
    for (int c = 0; c < 32; c++) { s0[c] = 0.f; s1[c] = 0.f; }

    #pragma unroll
    for (int ci = 0; ci < 16; ci++) {
        float v[6];
        #pragma unroll
        for (int j = 0; j < 6; j++) v[j] = buf[(2 * tid + j) * 16 + ci];
        #pragma unroll
        for (int k = 0; k < 5; k++) {
            const float4* wr = (const float4*)&ws[(ci * 5 + k) * 32];
            float a = v[k], bb = v[k + 1];
            #pragma unroll
            for (int q = 0; q < 8; q++) {
                float4 w4 = wr[q];
                s0[q*4+0] += w4.x * a;  s1[q*4+0] += w4.x * bb;
                s0[q*4+1] += w4.y * a;  s1[q*4+1] += w4.y * bb;
                s0[q*4+2] += w4.z * a;  s1[q*4+2] += w4.z * bb;
                s0[q*4+3] += w4.w * a;  s1[q*4+3] += w4.w * bb;
            }
        }
    }
    #pragma unroll
    for (int c = 0; c < 32; c++)
        h2s[c * 128 + tid] = fmaxf(fmaxf(s0[c], s1[c]) + bs[c], 0.f);
    __syncthreads();

    // reload buf with W1 (32x64)
    for (int j = tid; j < 2048; j += 128) buf[j] = w1g[j];
    __syncthreads();

    float acc[64];
    #pragma unroll
    for (int o = 0; o < 64; o++) acc[o] = 0.f;
    #pragma unroll
    for (int c = 0; c < 32; c++) {
        float v = h2s[c * 128 + tid];
        const float4* wr = (const float4*)&buf[c * 64];
        #pragma unroll
        for (int q = 0; q < 16; q++) {
            float4 w4 = wr[q];
            acc[q*4+0] += v * w4.x;
            acc[q*4+1] += v * w4.y;
            acc[q*4+2] += v * w4.z;
            acc[q*4+3] += v * w4.w;
        }
    }

    int n = b * TPP + tpb + tid;
    float dv = d_dinv[n];
    float4* outp = (float4*)(d_gA + (size_t)n * 64);
    #pragma unroll
    for (int q = 0; q < 16; q++)
        outp[q] = make_float4(acc[q*4+0]*dv, acc[q*4+1]*dv, acc[q*4+2]*dv, acc[q*4+3]*dv);
}

// ---------------- GCN gather: hB[c] = relu(dinv[c]*(gA[c] + sum gA[rows]) + b)
__global__ void gather_kernel(const float* __restrict__ bias) {
    int gw = (blockIdx.x * blockDim.x + threadIdx.x) >> 5;
    int lane = threadIdx.x & 31;
    if (gw >= NN) return;
    int p0 = d_ptr[gw];
    int p1 = p0 + d_cnt[gw];
    float dc = d_dinv[gw];
    const float2* gbase = (const float2*)d_gA;

    float2 acc = gbase[(size_t)gw * 32 + lane];   // self loop: g[c]*dinv[c]
    int e = p0;
    for (; e + 4 <= p1; e += 4) {
        int r0 = d_srow[e], r1 = d_srow[e+1], r2 = d_srow[e+2], r3 = d_srow[e+3];
        float2 v0 = gbase[(size_t)r0 * 32 + lane];
        float2 v1 = gbase[(size_t)r1 * 32 + lane];
        float2 v2 = gbase[(size_t)r2 * 32 + lane];
        float2 v3 = gbase[(size_t)r3 * 32 + lane];
        acc.x += (v0.x + v1.x) + (v2.x + v3.x);
        acc.y += (v0.y + v1.y) + (v2.y + v3.y);
    }
    for (; e < p1; e++) {
        int r = d_srow[e];
        float2 v = gbase[(size_t)r * 32 + lane];
        acc.x += v.x; acc.y += v.y;
    }
    float2 b2 = ((const float2*)bias)[lane];
    float2 o;
    o.x = fmaxf(dc * acc.x + b2.x, 0.f);
    o.y = fmaxf(dc * acc.y + b2.y, 0.f);
    ((float2*)d_hB)[(size_t)gw * 32 + lane] = o;
}

// ---------------- GEMM2: gA[n] = (hB[n] @ W2) * dinv[n] ---------------------
__global__ void gemm2_kernel(const float* __restrict__ w) {
    __shared__ __align__(16) float ws[64 * 64];
    int tid = threadIdx.x;
    for (int j = tid; j < 4096; j += 128) ws[j] = w[j];
    __syncthreads();

    int n = blockIdx.x * 128 + tid;
    const float4* hr = (const float4*)(d_hB + (size_t)n * 64);
    float acc[64];
    #pragma unroll
    for (int o = 0; o < 64; o++) acc[o] = 0.f;

    #pragma unroll
    for (int j = 0; j < 16; j++) {
        float4 hv = hr[j];
        #pragma unroll
        for (int s = 0; s < 4; s++) {
            int f = j * 4 + s;
            float v = (s == 0) ? hv.x : (s == 1) ? hv.y : (s == 2) ? hv.z : hv.w;
            const float4* wr = (const float4*)&ws[f * 64];
            #pragma unroll
            for (int q = 0; q < 16; q++) {
                float4 w4 = wr[q];
                acc[q*4+0] += v * w4.x;
                acc[q*4+1] += v * w4.y;
                acc[q*4+2] += v * w4.z;
                acc[q*4+3] += v * w4.w;
            }
        }
    }
    float dv = d_dinv[n];
    float4* outp = (float4*)(d_gA + (size_t)n * 64);
    #pragma unroll
    for (int q = 0; q < 16; q++)
        outp[q] = make_float4(acc[q*4+0]*dv, acc[q*4+1]*dv, acc[q*4+2]*dv, acc[q*4+3]*dv);
}

// ---------------- mean pool over TP + FC ------------------------------------
__global__ void pool_fc_kernel(const float* __restrict__ fcw,
                               const float* __restrict__ fcb,
                               float* __restrict__ out) {
    __shared__ float m[4][64];
    int b = blockIdx.x, tid = threadIdx.x;
    int f = tid & 63, q = tid >> 6;
    const float* hb = d_hB + (size_t)b * TPP * 64;
    float s = 0.f;
    for (int tp = q; tp < TPP; tp += 4) s += hb[tp * 64 + f];
    m[q][f] = s;
    __syncthreads();
    if (tid < 64) {
        float tot = (m[0][tid] + m[1][tid]) + (m[2][tid] + m[3][tid]);
        m[0][tid] = tot * (1.0f / TPP);
    }
    __syncthreads();
    if (tid < 6) {
        float acc = fcb[tid];
        #pragma unroll
        for (int k = 0; k < 64; k++) acc += m[0][k] * fcw[tid * 64 + k];
        out[b * 6 + tid] = acc;
    }
}

// ---------------- launch -----------------------------------------------------
extern "C" void kernel_launch(void* const* d_in, const int* in_sizes, int n_in,
                              void* d_out, int out_size) {
    const float* x   = (const float*)d_in[0];
    const int*   ei  = (const int*)  d_in[1];
    const float* w1  = (const float*)d_in[2];
    const float* b1  = (const float*)d_in[3];
    const float* w2  = (const float*)d_in[4];
    const float* b2  = (const float*)d_in[5];
    const float* g1w = (const float*)d_in[6];
    const float* g1b = (const float*)d_in[7];
    const float* g2w = (const float*)d_in[8];
    const float* g2b = (const float*)d_in[9];
    const float* fcw = (const float*)d_in[10];
    const float* fcb = (const float*)d_in[11];
    float* out = (float*)d_out;

    // graph prep (independent of conv stack)
    zero_cnt_kernel<<<NN / 1024, 1024>>>();
    hist_kernel<<<EE / 256, 256>>>(ei + EE);
    scan_block_kernel<<<NN / 1024, 1024>>>();
    scan_sums_kernel<<<1, 128>>>();
    finalize_kernel<<<NN / 1024, 1024>>>();
    scatter_kernel<<<EE / 256, 256>>>(ei, ei + EE);

    // conv stack + fused GEMM1
    conv1_kernel<<<dim3(8, BB), 128>>>(x, w1, b1);
    conv2_g1_kernel<<<dim3(4, BB), 128>>>(w2, b2, g1w);

    // GCN layer 1
    gather_kernel<<<NN * 32 / 256, 256>>>(g1b);
    // GCN layer 2
    gemm2_kernel<<<NN / 128, 128>>>(g2w);
    gather_kernel<<<NN * 32 / 256, 256>>>(g2b);

    // pool + fc
    pool_fc_kernel<<<BB, 256>>>(fcw, fcb, out);
}

// round 2
// speedup vs baseline: 1.0435x; 1.0435x over previous
#include <cuda_runtime.h>
#include <cstdint>

#define BB   256
#define TT   2048
#define FIN  9
#define T1   1024
#define TPP  512
#define NN   131072
#define EE   2097152
#define HID  64
#define TW   260

// ---------------- scratch (static device globals; no runtime alloc) ----------
__device__ int   d_cnt[NN];
__device__ int   d_ptr[NN];
__device__ int   d_cur[NN];
__device__ int   d_bsum[128];
__device__ int   d_srow[EE];
__device__ float d_dinv[NN];
__device__ float d_h1[(size_t)BB * T1 * 16];      // conv1 output (B, T1, 16)
__device__ float d_gA[(size_t)NN * HID];          // ping (also 32-dim phase)
__device__ float d_hB[(size_t)NN * HID];          // pong

// ---------------- streams/events for capture fork/join ----------------------
static cudaStream_t g_s2;
static cudaEvent_t  g_ev0, g_evFin, g_evScat;
namespace {
struct StreamInit {
    StreamInit() {
        cudaStreamCreateWithFlags(&g_s2, cudaStreamNonBlocking);
        cudaEventCreateWithFlags(&g_ev0,    cudaEventDisableTiming);
        cudaEventCreateWithFlags(&g_evFin,  cudaEventDisableTiming);
        cudaEventCreateWithFlags(&g_evScat, cudaEventDisableTiming);
    }
} g_streamInit;
}

// ---------------- graph prep -------------------------------------------------
__global__ void zero_cnt_kernel() {
    d_cnt[blockIdx.x * 1024 + threadIdx.x] = 0;
}

__global__ void hist_kernel(const int* __restrict__ col) {
    int e = blockIdx.x * blockDim.x + threadIdx.x;
    atomicAdd(&d_cnt[col[e]], 1);
}

__global__ void scan_block_kernel() {
    __shared__ int s[1024];
    int i = blockIdx.x * 1024 + threadIdx.x;
    int v = d_cnt[i];
    s[threadIdx.x] = v;
    __syncthreads();
    #pragma unroll
    for (int off = 1; off < 1024; off <<= 1) {
        int t = (threadIdx.x >= off) ? s[threadIdx.x - off] : 0;
        __syncthreads();
        s[threadIdx.x] += t;
        __syncthreads();
    }
    d_ptr[i] = s[threadIdx.x] - v;          // exclusive
    if (threadIdx.x == 1023) d_bsum[blockIdx.x] = s[1023];
}

__global__ void scan_sums_kernel() {
    __shared__ int s[128];
    int v = d_bsum[threadIdx.x];
    s[threadIdx.x] = v;
    __syncthreads();
    #pragma unroll
    for (int off = 1; off < 128; off <<= 1) {
        int t = (threadIdx.x >= off) ? s[threadIdx.x - off] : 0;
        __syncthreads();
        s[threadIdx.x] += t;
        __syncthreads();
    }
    d_bsum[threadIdx.x] = s[threadIdx.x] - v;  // exclusive block offsets
}

__global__ void finalize_kernel() {
    int i = blockIdx.x * 1024 + threadIdx.x;
    int p = d_ptr[i] + d_bsum[blockIdx.x];
    d_ptr[i] = p;
    d_cur[i] = p;
    d_dinv[i] = rsqrtf((float)d_cnt[i] + 1.0f);   // +1 for the self loop
}

__global__ void scatter_kernel(const int* __restrict__ row, const int* __restrict__ col) {
    int e = blockIdx.x * blockDim.x + threadIdx.x;
    int c = col[e];
    int p = atomicAdd(&d_cur[c], 1);
    d_srow[p] = row[e];
}

// ---------------- conv1: (B,T,9) -> relu -> pool2 -> (B,T1,16) ---------------
__global__ void conv1_kernel(const float* __restrict__ x,
                             const float* __restrict__ w,
                             const float* __restrict__ bias) {
    __shared__ __align__(16) float xs[TW * 9];
    __shared__ __align__(16) float ws[720];         // [(f*5+k)*16 + c]
    __shared__ float bs[16];
    int b = blockIdx.y, tp0 = blockIdx.x * 128, tid = threadIdx.x;

    for (int j = tid; j < 720; j += 128) {
        int c = j & 15, r = j >> 4, f = r / 5, k = r - f * 5;
        ws[j] = w[c * 45 + f * 5 + k];
    }
    if (tid < 16) bs[tid] = bias[tid];

    int base = 2 * tp0 - 2;
    const float* xb = x + (size_t)b * TT * FIN;
    for (int j = tid; j < TW * 9; j += 128) {
        int t = base + j / 9, f = j - (j / 9) * 9;
        xs[j] = (t >= 0 && t < TT) ? xb[t * 9 + f] : 0.0f;
    }
    __syncthreads();

    float s0[16], s1[16];
    #pragma unroll
    for (int c = 0; c < 16; c++) { s0[c] = 0.f; s1[c] = 0.f; }

    #pragma unroll
    for (int f = 0; f < 9; f++) {
        float v[6];
        #pragma unroll
        for (int j = 0; j < 6; j++) v[j] = xs[(2 * tid + j) * 9 + f];
        #pragma unroll
        for (int k = 0; k < 5; k++) {
            const float4* wr = (const float4*)&ws[(f * 5 + k) * 16];
            float a = v[k], bb = v[k + 1];
            #pragma unroll
            for (int q = 0; q < 4; q++) {
                float4 w4 = wr[q];
                s0[q*4+0] += w4.x * a;  s1[q*4+0] += w4.x * bb;
                s0[q*4+1] += w4.y * a;  s1[q*4+1] += w4.y * bb;
                s0[q*4+2] += w4.z * a;  s1[q*4+2] += w4.z * bb;
                s0[q*4+3] += w4.w * a;  s1[q*4+3] += w4.w * bb;
            }
        }
    }

    float4* out = (float4*)(d_h1 + ((size_t)b * T1 + tp0 + tid) * 16);
    #pragma unroll
    for (int q = 0; q < 4; q++) {
        float4 o;
        o.x = fmaxf(fmaxf(s0[q*4+0], s1[q*4+0]) + bs[q*4+0], 0.f);
        o.y = fmaxf(fmaxf(s0[q*4+1], s1[q*4+1]) + bs[q*4+1], 0.f);
        o.z = fmaxf(fmaxf(s0[q*4+2], s1[q*4+2]) + bs[q*4+2], 0.f);
        o.w = fmaxf(fmaxf(s0[q*4+3], s1[q*4+3]) + bs[q*4+3], 0.f);
        out[q] = o;
    }
}

// ------- conv2: h1 -> relu -> pool2 -> h2, writes g = dinv*h2 (32-dim) ------
__global__ void conv2_kernel(const float* __restrict__ w2,
                             const float* __restrict__ b2) {
    __shared__ __align__(16) float buf[TW * 16];
    __shared__ __align__(16) float ws[2560];        // [(ci*5+k)*32 + c]
    __shared__ float bs[32];
    int b = blockIdx.y, tpb = blockIdx.x * 128, tid = threadIdx.x;

    for (int j = tid; j < 2560; j += 128) {
        int c = j & 31, r = j >> 5, ci = r / 5, k = r - ci * 5;
        ws[j] = w2[c * 80 + ci * 5 + k];
    }
    if (tid < 32) bs[tid] = b2[tid];

    int base = 2 * tpb - 2;
    const float* hb = d_h1 + (size_t)b * T1 * 16;
    for (int j = tid; j < TW * 16; j += 128) {
        int t = base + (j >> 4);
        buf[j] = (t >= 0 && t < T1) ? hb[t * 16 + (j & 15)] : 0.0f;
    }
    __syncthreads();

    float s0[32], s1[32];
    #pragma unroll
    for (int c = 0; c < 32; c++) { s0[c] = 0.f; s1[c] = 0.f; }

    #pragma unroll
    for (int ci = 0; ci < 16; ci++) {
        float v[6];
        #pragma unroll
        for (int j = 0; j < 6; j++) v[j] = buf[(2 * tid + j) * 16 + ci];
        #pragma unroll
        for (int k = 0; k < 5; k++) {
            const float4* wr = (const float4*)&ws[(ci * 5 + k) * 32];
            float a = v[k], bb = v[k + 1];
            #pragma unroll
            for (int q = 0; q < 8; q++) {
                float4 w4 = wr[q];
                s0[q*4+0] += w4.x * a;  s1[q*4+0] += w4.x * bb;
                s0[q*4+1] += w4.y * a;  s1[q*4+1] += w4.y * bb;
                s0[q*4+2] += w4.z * a;  s1[q*4+2] += w4.z * bb;
                s0[q*4+3] += w4.w * a;  s1[q*4+3] += w4.w * bb;
            }
        }
    }

    int n = b * TPP + tpb + tid;
    float dv = d_dinv[n];
    float4* out = (float4*)(d_gA + (size_t)n * 32);
    #pragma unroll
    for (int q = 0; q < 8; q++) {
        float4 o;
        o.x = fmaxf(fmaxf(s0[q*4+0], s1[q*4+0]) + bs[q*4+0], 0.f) * dv;
        o.y = fmaxf(fmaxf(s0[q*4+1], s1[q*4+1]) + bs[q*4+1], 0.f) * dv;
        o.z = fmaxf(fmaxf(s0[q*4+2], s1[q*4+2]) + bs[q*4+2], 0.f) * dv;
        o.w = fmaxf(fmaxf(s0[q*4+3], s1[q*4+3]) + bs[q*4+3], 0.f) * dv;
        out[q] = o;
    }
}

// ------- gather1: 32-dim. acc1[c] = g[c] + sum_{e->c} g[row_e] -------------
__global__ void gather1_kernel() {
    int gw = (blockIdx.x * blockDim.x + threadIdx.x) >> 5;
    int lane = threadIdx.x & 31;
    int p0 = d_ptr[gw];
    int p1 = p0 + d_cnt[gw];
    const float* g = d_gA;

    float acc = g[(size_t)gw * 32 + lane];      // self loop
    int e = p0;
    for (; e + 8 <= p1; e += 8) {
        int r0 = d_srow[e],   r1 = d_srow[e+1], r2 = d_srow[e+2], r3 = d_srow[e+3];
        int r4 = d_srow[e+4], r5 = d_srow[e+5], r6 = d_srow[e+6], r7 = d_srow[e+7];
        float v0 = g[(size_t)r0 * 32 + lane];
        float v1 = g[(size_t)r1 * 32 + lane];
        float v2 = g[(size_t)r2 * 32 + lane];
        float v3 = g[(size_t)r3 * 32 + lane];
        float v4 = g[(size_t)r4 * 32 + lane];
        float v5 = g[(size_t)r5 * 32 + lane];
        float v6 = g[(size_t)r6 * 32 + lane];
        float v7 = g[(size_t)r7 * 32 + lane];
        acc += ((v0 + v1) + (v2 + v3)) + ((v4 + v5) + (v6 + v7));
    }
    for (; e < p1; e++) {
        acc += g[(size_t)d_srow[e] * 32 + lane];
    }
    d_hB[(size_t)gw * 32 + lane] = acc;
}

// ------- gemmA: gB = dinv * relu(dinv*(acc1@W1)+b1)   (32 -> 64) ------------
__global__ void gemmA_kernel(const float* __restrict__ w,
                             const float* __restrict__ bias) {
    __shared__ __align__(16) float ws[2048];
    __shared__ float bs[64];
    int tid = threadIdx.x;
    for (int j = tid; j < 2048; j += 128) ws[j] = w[j];
    if (tid < 64) bs[tid] = bias[tid];
    __syncthreads();

    int n = blockIdx.x * 128 + tid;
    const float4* ar = (const float4*)(d_hB + (size_t)n * 32);
    float acc[64];
    #pragma unroll
    for (int o = 0; o < 64; o++) acc[o] = 0.f;

    #pragma unroll
    for (int j = 0; j < 8; j++) {
        float4 av = ar[j];
        #pragma unroll
        for (int s = 0; s < 4; s++) {
            int c = j * 4 + s;
            float v = (s == 0) ? av.x : (s == 1) ? av.y : (s == 2) ? av.z : av.w;
            const float4* wr = (const float4*)&ws[c * 64];
            #pragma unroll
            for (int q = 0; q < 16; q++) {
                float4 w4 = wr[q];
                acc[q*4+0] += v * w4.x;
                acc[q*4+1] += v * w4.y;
                acc[q*4+2] += v * w4.z;
                acc[q*4+3] += v * w4.w;
            }
        }
    }
    float dv = d_dinv[n];
    float4* outp = (float4*)(d_gA + (size_t)n * 64);
    #pragma unroll
    for (int q = 0; q < 16; q++) {
        float4 o;
        o.x = fmaxf(dv * acc[q*4+0] + bs[q*4+0], 0.f) * dv;
        o.y = fmaxf(dv * acc[q*4+1] + bs[q*4+1], 0.f) * dv;
        o.z = fmaxf(dv * acc[q*4+2] + bs[q*4+2], 0.f) * dv;
        o.w = fmaxf(dv * acc[q*4+3] + bs[q*4+3], 0.f) * dv;
        outp[q] = o;
    }
}

// ------- gather2: 64-dim. acc2[c] = gB[c] + sum gB[row_e] -------------------
__global__ void gather2_kernel() {
    int gw = (blockIdx.x * blockDim.x + threadIdx.x) >> 5;
    int lane = threadIdx.x & 31;
    int p0 = d_ptr[gw];
    int p1 = p0 + d_cnt[gw];
    const float2* g = (const float2*)d_gA;

    float2 acc = g[(size_t)gw * 32 + lane];     // self loop
    int e = p0;
    for (; e + 4 <= p1; e += 4) {
        int r0 = d_srow[e], r1 = d_srow[e+1], r2 = d_srow[e+2], r3 = d_srow[e+3];
        float2 v0 = g[(size_t)r0 * 32 + lane];
        float2 v1 = g[(size_t)r1 * 32 + lane];
        float2 v2 = g[(size_t)r2 * 32 + lane];
        float2 v3 = g[(size_t)r3 * 32 + lane];
        acc.x += (v0.x + v1.x) + (v2.x + v3.x);
        acc.y += (v0.y + v1.y) + (v2.y + v3.y);
    }
    for (; e < p1; e++) {
        float2 v = g[(size_t)d_srow[e] * 32 + lane];
        acc.x += v.x; acc.y += v.y;
    }
    ((float2*)d_hB)[(size_t)gw * 32 + lane] = acc;
}

// ------- gemmB: out2 = relu(dinv*(acc2@W2)+b2)   (64 -> 64) -----------------
__global__ void gemmB_kernel(const float* __restrict__ w,
                             const float* __restrict__ bias) {
    __shared__ __align__(16) float ws[4096];
    __shared__ float bs[64];
    int tid = threadIdx.x;
    for (int j = tid; j < 4096; j += 128) ws[j] = w[j];
    if (tid < 64) bs[tid] = bias[tid];
    __syncthreads();

    int n = blockIdx.x * 128 + tid;
    const float4* ar = (const float4*)(d_hB + (size_t)n * 64);
    float acc[64];
    #pragma unroll
    for (int o = 0; o < 64; o++) acc[o] = 0.f;

    #pragma unroll
    for (int j = 0; j < 16; j++) {
        float4 av = ar[j];
        #pragma unroll
        for (int s = 0; s < 4; s++) {
            int c = j * 4 + s;
            float v = (s == 0) ? av.x : (s == 1) ? av.y : (s == 2) ? av.z : av.w;
            const float4* wr = (const float4*)&ws[c * 64];
            #pragma unroll
            for (int q = 0; q < 16; q++) {
                float4 w4 = wr[q];
                acc[q*4+0] += v * w4.x;
                acc[q*4+1] += v * w4.y;
                acc[q*4+2] += v * w4.z;
                acc[q*4+3] += v * w4.w;
            }
        }
    }
    float dv = d_dinv[n];
    float4* outp = (float4*)(d_gA + (size_t)n * 64);
    #pragma unroll
    for (int q = 0; q < 16; q++) {
        float4 o;
        o.x = fmaxf(dv * acc[q*4+0] + bs[q*4+0], 0.f);
        o.y = fmaxf(dv * acc[q*4+1] + bs[q*4+1], 0.f);
        o.z = fmaxf(dv * acc[q*4+2] + bs[q*4+2], 0.f);
        o.w = fmaxf(dv * acc[q*4+3] + bs[q*4+3], 0.f);
        outp[q] = o;
    }
}

// ---------------- mean pool over TP + FC ------------------------------------
__global__ void pool_fc_kernel(const float* __restrict__ fcw,
                               const float* __restrict__ fcb,
                               float* __restrict__ out) {
    __shared__ float m[4][64];
    int b = blockIdx.x, tid = threadIdx.x;
    int f = tid & 63, q = tid >> 6;
    const float* hb = d_gA + (size_t)b * TPP * 64;
    float s = 0.f;
    for (int tp = q; tp < TPP; tp += 4) s += hb[tp * 64 + f];
    m[q][f] = s;
    __syncthreads();
    if (tid < 64) {
        float tot = (m[0][tid] + m[1][tid]) + (m[2][tid] + m[3][tid]);
        m[0][tid] = tot * (1.0f / TPP);
    }
    __syncthreads();
    if (tid < 6) {
        float acc = fcb[tid];
        #pragma unroll
        for (int k = 0; k < 64; k++) acc += m[0][k] * fcw[tid * 64 + k];
        out[b * 6 + tid] = acc;
    }
}

// ---------------- launch -----------------------------------------------------
extern "C" void kernel_launch(void* const* d_in, const int* in_sizes, int n_in,
                              void* d_out, int out_size) {
    const float* x   = (const float*)d_in[0];
    const int*   ei  = (const int*)  d_in[1];
    const float* w1  = (const float*)d_in[2];
    const float* b1  = (const float*)d_in[3];
    const float* w2  = (const float*)d_in[4];
    const float* b2  = (const float*)d_in[5];
    const float* g1w = (const float*)d_in[6];
    const float* g1b = (const float*)d_in[7];
    const float* g2w = (const float*)d_in[8];
    const float* g2b = (const float*)d_in[9];
    const float* fcw = (const float*)d_in[10];
    const float* fcb = (const float*)d_in[11];
    float* out = (float*)d_out;

    // fork: graph prep on side stream, conv stack on main stream
    cudaEventRecord(g_ev0, 0);
    cudaStreamWaitEvent(g_s2, g_ev0, 0);

    zero_cnt_kernel<<<NN / 1024, 1024, 0, g_s2>>>();
    hist_kernel<<<EE / 256, 256, 0, g_s2>>>(ei + EE);
    scan_block_kernel<<<NN / 1024, 1024, 0, g_s2>>>();
    scan_sums_kernel<<<1, 128, 0, g_s2>>>();
    finalize_kernel<<<NN / 1024, 1024, 0, g_s2>>>();
    cudaEventRecord(g_evFin, g_s2);
    scatter_kernel<<<EE / 256, 256, 0, g_s2>>>(ei, ei + EE);
    cudaEventRecord(g_evScat, g_s2);

    // main stream: conv stack
    conv1_kernel<<<dim3(8, BB), 128>>>(x, w1, b1);
    cudaStreamWaitEvent(0, g_evFin, 0);           // conv2 needs dinv
    conv2_kernel<<<dim3(4, BB), 128>>>(w2, b2);
    cudaStreamWaitEvent(0, g_evScat, 0);          // gathers need CSR

    // GCN layer 1: aggregate 32-dim, then transform
    gather1_kernel<<<NN * 32 / 256, 256>>>();
    gemmA_kernel<<<NN / 128, 128>>>(g1w, g1b);

    // GCN layer 2: aggregate 64-dim, then transform
    gather2_kernel<<<NN * 32 / 256, 256>>>();
    gemmB_kernel<<<NN / 128, 128>>>(g2w, g2b);

    // pool + fc
    pool_fc_kernel<<<BB, 256>>>(fcw, fcb, out);
}